// round 7
// baseline (speedup 1.0000x reference)
#include <cuda_runtime.h>
#include <cuda_bf16.h>
#include <cstdint>

// ---------------------------------------------------------------------------
// MHA: x[4,2048,1024] -> QKV gemm -> 16-head flash attention -> proj gemm
// fp32 SIMT with packed fma.rn.f32x2 (Blackwell FFMA2) everywhere.
// ---------------------------------------------------------------------------

#define B_   4
#define T_   2048
#define D_   1024
#define H_   16
#define DK_  64
#define M_   (B_ * T_)          // 8192

// Scratch (allocation-free rule: __device__ globals)
__device__ float g_Q[B_ * H_ * T_ * DK_];   // 32 MB, pre-scaled by 1/sqrt(dk)
__device__ float g_K[B_ * H_ * T_ * DK_];
__device__ float g_V[B_ * H_ * T_ * DK_];
__device__ float g_O[B_ * T_ * D_];         // attention output, [B,T,D]

typedef unsigned long long ull;

__device__ __forceinline__ ull pack2(float x, float y) {
    ull r; asm("mov.b64 %0, {%1,%2};" : "=l"(r) : "f"(x), "f"(y)); return r;
}
__device__ __forceinline__ void unpack2(ull v, float &x, float &y) {
    asm("mov.b64 {%0,%1}, %2;" : "=f"(x), "=f"(y) : "l"(v));
}
// d = a*b + d on packed f32x2 (FFMA2)
__device__ __forceinline__ void fma2(ull &d, ull a, ull b) {
    asm("fma.rn.f32x2 %0, %1, %2, %0;" : "+l"(d) : "l"(a), "l"(b));
}
__device__ __forceinline__ void mul2(ull &d, ull a) {
    asm("mul.rn.f32x2 %0, %0, %1;" : "+l"(d) : "l"(a));
}

// ---------------------------------------------------------------------------
// Generic TN GEMM: C[M,N] = A[M,K] @ Bw[N,K]^T
// BM=BN=128, BK=16, 256 threads, 8x8 per thread (packed into 8x4 f32x2 accums)
// mode 0: A = x, scatter C into g_Q/g_K/g_V head layout (Q scaled by 0.125)
// mode 1: A = g_O, write C to out
// ---------------------------------------------------------------------------
__global__ __launch_bounds__(256, 2)
void gemm_tn_kernel(const float* __restrict__ A, const float* __restrict__ Bw,
                    float* __restrict__ out, int M, int N, int K, int mode)
{
    __shared__ __align__(16) float As[16][132];
    __shared__ __align__(16) float Bs[16][132];

    const float* __restrict__ Ap = (mode == 1) ? (const float*)g_O : A;

    const int m0 = blockIdx.y * 128;
    const int n0 = blockIdx.x * 128;
    const int tid = threadIdx.x;
    const int ttx = tid & 15;       // column block (8 cols)
    const int tty = tid >> 4;       // row block    (8 rows)

    ull acc[8][4];
#pragma unroll
    for (int i = 0; i < 8; i++)
#pragma unroll
        for (int j = 0; j < 4; j++) acc[i][j] = 0ull;

    for (int k0 = 0; k0 < K; k0 += 16) {
        __syncthreads();
#pragma unroll
        for (int i = 0; i < 2; i++) {
            int v  = tid + i * 256;      // 0..511
            int r  = v >> 2;             // 0..127
            int c4 = (v & 3) * 4;        // 0,4,8,12
            float4 av = *(const float4*)(Ap + (size_t)(m0 + r) * K + k0 + c4);
            As[c4 + 0][r] = av.x; As[c4 + 1][r] = av.y;
            As[c4 + 2][r] = av.z; As[c4 + 3][r] = av.w;
            float4 bv = *(const float4*)(Bw + (size_t)(n0 + r) * K + k0 + c4);
            Bs[c4 + 0][r] = bv.x; Bs[c4 + 1][r] = bv.y;
            Bs[c4 + 2][r] = bv.z; Bs[c4 + 3][r] = bv.w;
        }
        __syncthreads();

#pragma unroll
        for (int k = 0; k < 16; k++) {
            float4 a0 = *(const float4*)&As[k][tty * 8];
            float4 a1 = *(const float4*)&As[k][tty * 8 + 4];
            float4 b0 = *(const float4*)&Bs[k][ttx * 8];
            float4 b1 = *(const float4*)&Bs[k][ttx * 8 + 4];
            ull bb0 = pack2(b0.x, b0.y), bb1 = pack2(b0.z, b0.w);
            ull bb2 = pack2(b1.x, b1.y), bb3 = pack2(b1.z, b1.w);
            float av[8] = {a0.x, a0.y, a0.z, a0.w, a1.x, a1.y, a1.z, a1.w};
#pragma unroll
            for (int i = 0; i < 8; i++) {
                ull ad = pack2(av[i], av[i]);
                fma2(acc[i][0], ad, bb0);
                fma2(acc[i][1], ad, bb1);
                fma2(acc[i][2], ad, bb2);
                fma2(acc[i][3], ad, bb3);
            }
        }
    }

#pragma unroll
    for (int i = 0; i < 8; i++) {
        float c[8];
        unpack2(acc[i][0], c[0], c[1]); unpack2(acc[i][1], c[2], c[3]);
        unpack2(acc[i][2], c[4], c[5]); unpack2(acc[i][3], c[6], c[7]);
        int m = m0 + tty * 8 + i;
        if (mode == 0) {
            int b = m >> 11, t = m & 2047;
#pragma unroll
            for (int j = 0; j < 8; j++) {
                int n = n0 + ttx * 8 + j;
                int which = n >> 10;
                int rem = n & 1023;
                int h = rem >> 6, dd = rem & 63;
                size_t idx = ((size_t)((b << 4) + h) * T_ + t) * DK_ + dd;
                if (which == 0)       g_Q[idx] = c[j] * 0.125f;  // 1/sqrt(64)
                else if (which == 1)  g_K[idx] = c[j];
                else                  g_V[idx] = c[j];
            }
        } else {
            float* o = out + (size_t)m * N + n0 + ttx * 8;
            *(float4*)(o)     = make_float4(c[0], c[1], c[2], c[3]);
            *(float4*)(o + 4) = make_float4(c[4], c[5], c[6], c[7]);
        }
    }
}

// ---------------------------------------------------------------------------
// Flash attention: one block per (bh, 128-row Q tile). Bc = 64 keys per step.
// SMEM: Qs[128][68] rowmajor | Kt[64(d)][68] transposed | Vs[64][68] rowmajor
//       Ps[128][68] rowmajor.  Thread grid 16x16: 8 rows x 4 cols per thread.
// ---------------------------------------------------------------------------
#define QS_OFF 0
#define KT_OFF 8704                  // 128*68
#define VS_OFF (8704 + 4352)         // + 64*68
#define PS_OFF (8704 + 4352 + 4352)
#define ATTN_SMEM_FLOATS (8704 + 4352 + 4352 + 8704)
#define ATTN_SMEM_BYTES  (ATTN_SMEM_FLOATS * 4)   // 104448

__global__ __launch_bounds__(256, 2)
void attn_kernel()
{
    extern __shared__ __align__(16) float sm[];
    float* Qs = sm + QS_OFF;
    float* Kt = sm + KT_OFF;
    float* Vs = sm + VS_OFF;
    float* Ps = sm + PS_OFF;

    const int qt = blockIdx.x;       // 0..15
    const int bh = blockIdx.y;       // 0..63
    const float* __restrict__ Qg = g_Q + (size_t)bh * (T_ * DK_) + (size_t)qt * (128 * DK_);
    const float* __restrict__ Kg = g_K + (size_t)bh * (T_ * DK_);
    const float* __restrict__ Vg = g_V + (size_t)bh * (T_ * DK_);

    const int tid = threadIdx.x;
    const int ttx = tid & 15;        // 4 cols each
    const int tty = tid >> 4;        // 8 rows each

    // Load Q tile (128x64) once
#pragma unroll
    for (int i = 0; i < 8; i++) {
        int v  = tid + i * 256;
        int r  = v >> 4;
        int c4 = (v & 15) * 4;
        *(float4*)&Qs[r * 68 + c4] = *(const float4*)(Qg + r * 64 + c4);
    }

    ull O2[8][2];
    float mrow[8], lrow[8];
#pragma unroll
    for (int i = 0; i < 8; i++) {
        O2[i][0] = 0ull; O2[i][1] = 0ull;
        mrow[i] = -1e30f; lrow[i] = 0.0f;
    }

    for (int kt = 0; kt < T_ / 64; kt++) {
        __syncthreads();   // previous PV reads of Vs/Ps done
        // Load K (transposed) and V tiles, 64x64 each
#pragma unroll
        for (int i = 0; i < 4; i++) {
            int v  = tid + i * 256;
            int r  = v >> 4;             // key index 0..63
            int c4 = (v & 15) * 4;       // d
            float4 kk = *(const float4*)(Kg + kt * 4096 + r * 64 + c4);
            Kt[(c4 + 0) * 68 + r] = kk.x;
            Kt[(c4 + 1) * 68 + r] = kk.y;
            Kt[(c4 + 2) * 68 + r] = kk.z;
            Kt[(c4 + 3) * 68 + r] = kk.w;
            *(float4*)&Vs[r * 68 + c4] = *(const float4*)(Vg + kt * 4096 + r * 64 + c4);
        }
        __syncthreads();

        // S = Q @ K^T, per-thread 8 rows x 4 cols (packed 8x2)
        ull s2[8][2];
#pragma unroll
        for (int i = 0; i < 8; i++) { s2[i][0] = 0ull; s2[i][1] = 0ull; }
#pragma unroll 8
        for (int d = 0; d < 64; d++) {
            float4 kv = *(const float4*)&Kt[d * 68 + ttx * 4];
            ull b0 = pack2(kv.x, kv.y), b1 = pack2(kv.z, kv.w);
#pragma unroll
            for (int i = 0; i < 8; i++) {
                float a = Qs[(tty * 8 + i) * 68 + d];
                ull ad = pack2(a, a);
                fma2(s2[i][0], ad, b0);
                fma2(s2[i][1], ad, b1);
            }
        }

        // Online softmax per row; write P to SMEM
#pragma unroll
        for (int i = 0; i < 8; i++) {
            float p0, p1, p2, p3;
            unpack2(s2[i][0], p0, p1);
            unpack2(s2[i][1], p2, p3);
            float v = fmaxf(fmaxf(p0, p1), fmaxf(p2, p3));
            v = fmaxf(v, __shfl_xor_sync(0xffffffffu, v, 8));
            v = fmaxf(v, __shfl_xor_sync(0xffffffffu, v, 4));
            v = fmaxf(v, __shfl_xor_sync(0xffffffffu, v, 2));
            v = fmaxf(v, __shfl_xor_sync(0xffffffffu, v, 1));
            float mn = fmaxf(mrow[i], v);
            float alpha = __expf(mrow[i] - mn);
            mrow[i] = mn;
            p0 = __expf(p0 - mn); p1 = __expf(p1 - mn);
            p2 = __expf(p2 - mn); p3 = __expf(p3 - mn);
            float rs = (p0 + p1) + (p2 + p3);
            rs += __shfl_xor_sync(0xffffffffu, rs, 8);
            rs += __shfl_xor_sync(0xffffffffu, rs, 4);
            rs += __shfl_xor_sync(0xffffffffu, rs, 2);
            rs += __shfl_xor_sync(0xffffffffu, rs, 1);
            lrow[i] = lrow[i] * alpha + rs;
            ull am = pack2(alpha, alpha);
            mul2(O2[i][0], am);
            mul2(O2[i][1], am);
            *(float4*)&Ps[(tty * 8 + i) * 68 + ttx * 4] = make_float4(p0, p1, p2, p3);
        }
        __syncthreads();

        // O += P @ V
#pragma unroll 8
        for (int j = 0; j < 64; j++) {
            float4 vv = *(const float4*)&Vs[j * 68 + ttx * 4];
            ull b0 = pack2(vv.x, vv.y), b1 = pack2(vv.z, vv.w);
#pragma unroll
            for (int i = 0; i < 8; i++) {
                float a = Ps[(tty * 8 + i) * 68 + j];
                ull ad = pack2(a, a);
                fma2(O2[i][0], ad, b0);
                fma2(O2[i][1], ad, b1);
            }
        }
    }

    // Normalize and store to g_O in [B,T,D] layout
    const int b = bh >> 4, h = bh & 15;
#pragma unroll
    for (int i = 0; i < 8; i++) {
        float o0, o1, o2, o3;
        unpack2(O2[i][0], o0, o1);
        unpack2(O2[i][1], o2, o3);
        float inv = 1.0f / lrow[i];
        int t = qt * 128 + tty * 8 + i;
        *(float4*)&g_O[((size_t)(b * T_ + t)) * D_ + h * 64 + ttx * 4]
            = make_float4(o0 * inv, o1 * inv, o2 * inv, o3 * inv);
    }
}

// ---------------------------------------------------------------------------
extern "C" void kernel_launch(void* const* d_in, const int* in_sizes, int n_in,
                              void* d_out, int out_size)
{
    const float* x      = (const float*)d_in[0];   // [4,2048,1024]
    const float* W_qkv  = (const float*)d_in[1];   // [3072,1024]
    const float* W_proj = (const float*)d_in[2];   // [1024,1024]
    float* out = (float*)d_out;                    // [4,2048,1024]

    cudaFuncSetAttribute(attn_kernel,
                         cudaFuncAttributeMaxDynamicSharedMemorySize,
                         ATTN_SMEM_BYTES);

    // 1) QKV GEMM + head-layout scatter (Q pre-scaled)
    dim3 g1(3 * D_ / 128, M_ / 128);   // (24, 64)
    gemm_tn_kernel<<<g1, 256>>>(x, W_qkv, nullptr, M_, 3 * D_, D_, 0);

    // 2) Flash attention
    dim3 g2(T_ / 128, B_ * H_);        // (16, 64)
    attn_kernel<<<g2, 256, ATTN_SMEM_BYTES>>>();

    // 3) Output projection
    dim3 g3(D_ / 128, M_ / 128);       // (8, 64)
    gemm_tn_kernel<<<g3, 256>>>(nullptr, W_proj, out, M_, D_, D_, 1);
}

// round 8
// speedup vs baseline: 1.0006x; 1.0006x over previous
#include <cuda_runtime.h>
#include <cuda_bf16.h>
#include <cstdint>

// ---------------------------------------------------------------------------
// MHA: x[4,2048,1024] -> QKV gemm -> 16-head flash attention -> proj gemm
// fp32 SIMT with packed fma.rn.f32x2 (Blackwell FFMA2) everywhere.
// ---------------------------------------------------------------------------

#define B_   4
#define T_   2048
#define D_   1024
#define H_   16
#define DK_  64
#define M_   (B_ * T_)          // 8192

// Scratch (allocation-free rule: __device__ globals)
__device__ float g_Q[B_ * H_ * T_ * DK_];   // 32 MB, pre-scaled by 1/sqrt(dk)
__device__ float g_K[B_ * H_ * T_ * DK_];
__device__ float g_V[B_ * H_ * T_ * DK_];
__device__ float g_O[B_ * T_ * D_];         // attention output, [B,T,D]

typedef unsigned long long ull;

__device__ __forceinline__ ull pack2(float x, float y) {
    ull r; asm("mov.b64 %0, {%1,%2};" : "=l"(r) : "f"(x), "f"(y)); return r;
}
__device__ __forceinline__ void unpack2(ull v, float &x, float &y) {
    asm("mov.b64 {%0,%1}, %2;" : "=f"(x), "=f"(y) : "l"(v));
}
// d = a*b + d on packed f32x2 (FFMA2)
__device__ __forceinline__ void fma2(ull &d, ull a, ull b) {
    asm("fma.rn.f32x2 %0, %1, %2, %0;" : "+l"(d) : "l"(a), "l"(b));
}
__device__ __forceinline__ void mul2(ull &d, ull a) {
    asm("mul.rn.f32x2 %0, %0, %1;" : "+l"(d) : "l"(a));
}

// ---------------------------------------------------------------------------
// Generic TN GEMM: C[M,N] = A[M,K] @ Bw[N,K]^T
// BM=BN=128, BK=16, 256 threads, 8x8 per thread (packed into 8x4 f32x2 accums)
// mode 0: A = x, scatter C into g_Q/g_K/g_V head layout (Q scaled by 0.125)
// mode 1: A = g_O, write C to out
// ---------------------------------------------------------------------------
__global__ __launch_bounds__(256, 2)
void gemm_tn_kernel(const float* __restrict__ A, const float* __restrict__ Bw,
                    float* __restrict__ out, int M, int N, int K, int mode)
{
    __shared__ __align__(16) float As[16][132];
    __shared__ __align__(16) float Bs[16][132];

    const float* __restrict__ Ap = (mode == 1) ? (const float*)g_O : A;

    const int m0 = blockIdx.y * 128;
    const int n0 = blockIdx.x * 128;
    const int tid = threadIdx.x;
    const int ttx = tid & 15;       // column block (8 cols)
    const int tty = tid >> 4;       // row block    (8 rows)

    ull acc[8][4];
#pragma unroll
    for (int i = 0; i < 8; i++)
#pragma unroll
        for (int j = 0; j < 4; j++) acc[i][j] = 0ull;

    for (int k0 = 0; k0 < K; k0 += 16) {
        __syncthreads();
#pragma unroll
        for (int i = 0; i < 2; i++) {
            int v  = tid + i * 256;      // 0..511
            int r  = v >> 2;             // 0..127
            int c4 = (v & 3) * 4;        // 0,4,8,12
            float4 av = *(const float4*)(Ap + (size_t)(m0 + r) * K + k0 + c4);
            As[c4 + 0][r] = av.x; As[c4 + 1][r] = av.y;
            As[c4 + 2][r] = av.z; As[c4 + 3][r] = av.w;
            float4 bv = *(const float4*)(Bw + (size_t)(n0 + r) * K + k0 + c4);
            Bs[c4 + 0][r] = bv.x; Bs[c4 + 1][r] = bv.y;
            Bs[c4 + 2][r] = bv.z; Bs[c4 + 3][r] = bv.w;
        }
        __syncthreads();

#pragma unroll
        for (int k = 0; k < 16; k++) {
            float4 a0 = *(const float4*)&As[k][tty * 8];
            float4 a1 = *(const float4*)&As[k][tty * 8 + 4];
            float4 b0 = *(const float4*)&Bs[k][ttx * 8];
            float4 b1 = *(const float4*)&Bs[k][ttx * 8 + 4];
            ull bb0 = pack2(b0.x, b0.y), bb1 = pack2(b0.z, b0.w);
            ull bb2 = pack2(b1.x, b1.y), bb3 = pack2(b1.z, b1.w);
            float av[8] = {a0.x, a0.y, a0.z, a0.w, a1.x, a1.y, a1.z, a1.w};
#pragma unroll
            for (int i = 0; i < 8; i++) {
                ull ad = pack2(av[i], av[i]);
                fma2(acc[i][0], ad, bb0);
                fma2(acc[i][1], ad, bb1);
                fma2(acc[i][2], ad, bb2);
                fma2(acc[i][3], ad, bb3);
            }
        }
    }

#pragma unroll
    for (int i = 0; i < 8; i++) {
        float c[8];
        unpack2(acc[i][0], c[0], c[1]); unpack2(acc[i][1], c[2], c[3]);
        unpack2(acc[i][2], c[4], c[5]); unpack2(acc[i][3], c[6], c[7]);
        int m = m0 + tty * 8 + i;
        if (mode == 0) {
            int b = m >> 11, t = m & 2047;
#pragma unroll
            for (int j = 0; j < 8; j++) {
                int n = n0 + ttx * 8 + j;
                int which = n >> 10;
                int rem = n & 1023;
                int h = rem >> 6, dd = rem & 63;
                size_t idx = ((size_t)((b << 4) + h) * T_ + t) * DK_ + dd;
                if (which == 0)       g_Q[idx] = c[j] * 0.125f;  // 1/sqrt(64)
                else if (which == 1)  g_K[idx] = c[j];
                else                  g_V[idx] = c[j];
            }
        } else {
            float* o = out + (size_t)m * N + n0 + ttx * 8;
            *(float4*)(o)     = make_float4(c[0], c[1], c[2], c[3]);
            *(float4*)(o + 4) = make_float4(c[4], c[5], c[6], c[7]);
        }
    }
}

// ---------------------------------------------------------------------------
// Flash attention: one block per (bh, 128-row Q tile). Bc = 64 keys per step.
// SMEM: Qs[128][68] rowmajor | Kt[64(d)][68] transposed | Vs[64][68] rowmajor
//       Ps[128][68] rowmajor.  Thread grid 16x16: 8 rows x 4 cols per thread.
// ---------------------------------------------------------------------------
#define QS_OFF 0
#define KT_OFF 8704                  // 128*68
#define VS_OFF (8704 + 4352)         // + 64*68
#define PS_OFF (8704 + 4352 + 4352)
#define ATTN_SMEM_FLOATS (8704 + 4352 + 4352 + 8704)
#define ATTN_SMEM_BYTES  (ATTN_SMEM_FLOATS * 4)   // 104448

__global__ __launch_bounds__(256, 2)
void attn_kernel()
{
    extern __shared__ __align__(16) float sm[];
    float* Qs = sm + QS_OFF;
    float* Kt = sm + KT_OFF;
    float* Vs = sm + VS_OFF;
    float* Ps = sm + PS_OFF;

    const int qt = blockIdx.x;       // 0..15
    const int bh = blockIdx.y;       // 0..63
    const float* __restrict__ Qg = g_Q + (size_t)bh * (T_ * DK_) + (size_t)qt * (128 * DK_);
    const float* __restrict__ Kg = g_K + (size_t)bh * (T_ * DK_);
    const float* __restrict__ Vg = g_V + (size_t)bh * (T_ * DK_);

    const int tid = threadIdx.x;
    const int ttx = tid & 15;        // 4 cols each
    const int tty = tid >> 4;        // 8 rows each

    // Load Q tile (128x64) once
#pragma unroll
    for (int i = 0; i < 8; i++) {
        int v  = tid + i * 256;
        int r  = v >> 4;
        int c4 = (v & 15) * 4;
        *(float4*)&Qs[r * 68 + c4] = *(const float4*)(Qg + r * 64 + c4);
    }

    ull O2[8][2];
    float mrow[8], lrow[8];
#pragma unroll
    for (int i = 0; i < 8; i++) {
        O2[i][0] = 0ull; O2[i][1] = 0ull;
        mrow[i] = -1e30f; lrow[i] = 0.0f;
    }

    for (int kt = 0; kt < T_ / 64; kt++) {
        __syncthreads();   // previous PV reads of Vs/Ps done
        // Load K (transposed) and V tiles, 64x64 each
#pragma unroll
        for (int i = 0; i < 4; i++) {
            int v  = tid + i * 256;
            int r  = v >> 4;             // key index 0..63
            int c4 = (v & 15) * 4;       // d
            float4 kk = *(const float4*)(Kg + kt * 4096 + r * 64 + c4);
            Kt[(c4 + 0) * 68 + r] = kk.x;
            Kt[(c4 + 1) * 68 + r] = kk.y;
            Kt[(c4 + 2) * 68 + r] = kk.z;
            Kt[(c4 + 3) * 68 + r] = kk.w;
            *(float4*)&Vs[r * 68 + c4] = *(const float4*)(Vg + kt * 4096 + r * 64 + c4);
        }
        __syncthreads();

        // S = Q @ K^T, per-thread 8 rows x 4 cols (packed 8x2)
        ull s2[8][2];
#pragma unroll
        for (int i = 0; i < 8; i++) { s2[i][0] = 0ull; s2[i][1] = 0ull; }
#pragma unroll 8
        for (int d = 0; d < 64; d++) {
            float4 kv = *(const float4*)&Kt[d * 68 + ttx * 4];
            ull b0 = pack2(kv.x, kv.y), b1 = pack2(kv.z, kv.w);
#pragma unroll
            for (int i = 0; i < 8; i++) {
                float a = Qs[(tty * 8 + i) * 68 + d];
                ull ad = pack2(a, a);
                fma2(s2[i][0], ad, b0);
                fma2(s2[i][1], ad, b1);
            }
        }

        // Online softmax per row; write P to SMEM
#pragma unroll
        for (int i = 0; i < 8; i++) {
            float p0, p1, p2, p3;
            unpack2(s2[i][0], p0, p1);
            unpack2(s2[i][1], p2, p3);
            float v = fmaxf(fmaxf(p0, p1), fmaxf(p2, p3));
            v = fmaxf(v, __shfl_xor_sync(0xffffffffu, v, 8));
            v = fmaxf(v, __shfl_xor_sync(0xffffffffu, v, 4));
            v = fmaxf(v, __shfl_xor_sync(0xffffffffu, v, 2));
            v = fmaxf(v, __shfl_xor_sync(0xffffffffu, v, 1));
            float mn = fmaxf(mrow[i], v);
            float alpha = __expf(mrow[i] - mn);
            mrow[i] = mn;
            p0 = __expf(p0 - mn); p1 = __expf(p1 - mn);
            p2 = __expf(p2 - mn); p3 = __expf(p3 - mn);
            float rs = (p0 + p1) + (p2 + p3);
            rs += __shfl_xor_sync(0xffffffffu, rs, 8);
            rs += __shfl_xor_sync(0xffffffffu, rs, 4);
            rs += __shfl_xor_sync(0xffffffffu, rs, 2);
            rs += __shfl_xor_sync(0xffffffffu, rs, 1);
            lrow[i] = lrow[i] * alpha + rs;
            ull am = pack2(alpha, alpha);
            mul2(O2[i][0], am);
            mul2(O2[i][1], am);
            *(float4*)&Ps[(tty * 8 + i) * 68 + ttx * 4] = make_float4(p0, p1, p2, p3);
        }
        __syncthreads();

        // O += P @ V
#pragma unroll 8
        for (int j = 0; j < 64; j++) {
            float4 vv = *(const float4*)&Vs[j * 68 + ttx * 4];
            ull b0 = pack2(vv.x, vv.y), b1 = pack2(vv.z, vv.w);
#pragma unroll
            for (int i = 0; i < 8; i++) {
                float a = Ps[(tty * 8 + i) * 68 + j];
                ull ad = pack2(a, a);
                fma2(O2[i][0], ad, b0);
                fma2(O2[i][1], ad, b1);
            }
        }
    }

    // Normalize and store to g_O in [B,T,D] layout
    const int b = bh >> 4, h = bh & 15;
#pragma unroll
    for (int i = 0; i < 8; i++) {
        float o0, o1, o2, o3;
        unpack2(O2[i][0], o0, o1);
        unpack2(O2[i][1], o2, o3);
        float inv = 1.0f / lrow[i];
        int t = qt * 128 + tty * 8 + i;
        *(float4*)&g_O[((size_t)(b * T_ + t)) * D_ + h * 64 + ttx * 4]
            = make_float4(o0 * inv, o1 * inv, o2 * inv, o3 * inv);
    }
}

// ---------------------------------------------------------------------------
extern "C" void kernel_launch(void* const* d_in, const int* in_sizes, int n_in,
                              void* d_out, int out_size)
{
    const float* x      = (const float*)d_in[0];   // [4,2048,1024]
    const float* W_qkv  = (const float*)d_in[1];   // [3072,1024]
    const float* W_proj = (const float*)d_in[2];   // [1024,1024]
    float* out = (float*)d_out;                    // [4,2048,1024]

    cudaFuncSetAttribute(attn_kernel,
                         cudaFuncAttributeMaxDynamicSharedMemorySize,
                         ATTN_SMEM_BYTES);

    // 1) QKV GEMM + head-layout scatter (Q pre-scaled)
    dim3 g1(3 * D_ / 128, M_ / 128);   // (24, 64)
    gemm_tn_kernel<<<g1, 256>>>(x, W_qkv, nullptr, M_, 3 * D_, D_, 0);

    // 2) Flash attention
    dim3 g2(T_ / 128, B_ * H_);        // (16, 64)
    attn_kernel<<<g2, 256, ATTN_SMEM_BYTES>>>();

    // 3) Output projection
    dim3 g3(D_ / 128, M_ / 128);       // (8, 64)
    gemm_tn_kernel<<<g3, 256>>>(nullptr, W_proj, out, M_, D_, D_, 1);
}